// round 1
// baseline (speedup 1.0000x reference)
#include <cuda_runtime.h>

#define BATCH 32
#define HH 256
#define WW 256
#define CC 16
#define KK 32
#define NSTEPS 5
#define NPIX (BATCH*HH*WW)           // 2097152
#define NELEM (NPIX*CC)              // 33554432

// ---------------- static device scratch (no allocations allowed) ----------------
__device__ float g_M[9*CC*KK];       // [tap][c][k]: up1_w[:, :, tap] @ codebook[k]
__device__ float g_P[CC*KK];         // beta*cb  (per channel c, code k)
__device__ float g_Q[CC*KK];         // 1 - beta
__device__ float g_cbT[CC*KK];       // codebook transposed [c][k]
__device__ float g_csq[KK];          // ||cb_k||^2
__device__ float g_sigD[KK];         // sigmoid(dec_w . cb_k + dec_b)
__device__ float g_sse[NSTEPS];
__device__ unsigned g_used[NSTEPS];
__device__ unsigned char g_idxA[NPIX];
__device__ unsigned char g_idxB[NPIX];

// ---------------- table precompute + accumulator reset ----------------
__global__ void k_tables(const float* __restrict__ up1_w,
                         const float* __restrict__ tau_w, const float* __restrict__ tau_b,
                         const float* __restrict__ cb,
                         const float* __restrict__ dec_w, const float* __restrict__ dec_b) {
    int tid = threadIdx.x;
    for (int e = tid; e < 9*CC*KK; e += blockDim.x) {
        int k = e & 31; int c = (e >> 5) & 15; int tap = e >> 9;
        float acc = 0.f;
        #pragma unroll
        for (int ci = 0; ci < CC; ci++)
            acc = fmaf(up1_w[(c*CC+ci)*9 + tap], cb[k*CC+ci], acc);
        g_M[e] = acc;
    }
    for (int e = tid; e < CC*KK; e += blockDim.x) {
        int k = e & 31; int c = e >> 5;
        float t = tau_b[c];
        #pragma unroll
        for (int ci = 0; ci < CC; ci++)
            t = fmaf(tau_w[c*CC+ci], cb[k*CC+ci], t);
        float beta = 1.f / (1.f + expf(-t));
        float cv = cb[k*CC+c];
        g_P[e] = beta * cv;
        g_Q[e] = 1.f - beta;
        g_cbT[e] = cv;
    }
    for (int k = tid; k < KK; k += blockDim.x) {
        float s = 0.f, d = dec_b[0];
        #pragma unroll
        for (int c = 0; c < CC; c++) { float v = cb[k*CC+c]; s = fmaf(v, v, s); d = fmaf(dec_w[c], v, d); }
        g_csq[k] = s;
        g_sigD[k] = 1.f / (1.f + expf(-d));
    }
    if (tid < NSTEPS) { g_sse[tid] = 0.f; g_used[tid] = 0u; }
}

// ---------------- VQ helper: argmin over K codes (first-min, matches jnp.argmin) ----------------
__device__ __forceinline__ int vq_argmin(const float* z, float& loss) {
    float zsq = 0.f;
    #pragma unroll
    for (int c = 0; c < CC; c++) zsq = fmaf(z[c], z[c], zsq);
    float best = 3.4e38f; int bk = 0;
    #pragma unroll 4
    for (int k = 0; k < KK; k++) {
        float dot = 0.f;
        #pragma unroll
        for (int c = 0; c < CC; c++) dot = fmaf(z[c], g_cbT[c*KK+k], dot);
        float score = zsq + g_csq[k] - 2.f*dot;
        if (score < best) { best = score; bk = k; }
    }
    float l = 0.f;
    #pragma unroll
    for (int c = 0; c < CC; c++) { float d = z[c] - g_cbT[c*KK+bk]; l = fmaf(d, d, l); }
    loss = l;
    return bk;
}

__device__ __forceinline__ void block_accumulate(float loss, int bk, int slot,
                                                 float* red, unsigned* redu) {
    unsigned mask = 1u << bk;
    #pragma unroll
    for (int o = 16; o; o >>= 1) loss += __shfl_xor_sync(0xffffffffu, loss, o);
    mask = __reduce_or_sync(0xffffffffu, mask);
    int lane = threadIdx.x & 31, wid = threadIdx.x >> 5;
    if (lane == 0) { red[wid] = loss; redu[wid] = mask; }
    __syncthreads();
    if (threadIdx.x == 0) {
        float s = 0.f; unsigned m = 0u;
        int nw = blockDim.x >> 5;
        for (int i = 0; i < nw; i++) { s += red[i]; m |= redu[i]; }
        atomicAdd(&g_sse[slot], s);
        atomicOr(&g_used[slot], m);
    }
}

// ---------------- fused stem + step 1 (full fp32 path, never materializes state0) ----------------
__global__ __launch_bounds__(256)
void k_step1(const float* __restrict__ x,
             const float* __restrict__ stem_w, const float* __restrict__ stem_b,
             const float* __restrict__ up1_w, const float* __restrict__ up1_b,
             const float* __restrict__ up2_w, const float* __restrict__ up2_b,
             const float* __restrict__ tau_w, const float* __restrict__ tau_b) {
    __shared__ float xs[20*20];
    __shared__ float s0[CC][18*18];
    __shared__ float w1s[CC*9*CC];    // [ci][tap][co], co contiguous for float4 loads
    __shared__ float red[8]; __shared__ unsigned redu[8];

    int tid = threadIdx.x;
    int tx = tid & 15, ty = tid >> 4;
    int gx0 = blockIdx.x * 16, gy0 = blockIdx.y * 16, b = blockIdx.z;
    const float* xb = x + b * HH * WW;

    for (int p = tid; p < 400; p += 256) {
        int iy = p / 20, ix = p % 20;
        int gy = gy0 - 2 + iy, gx = gx0 - 2 + ix;
        xs[p] = (gy >= 0 && gy < HH && gx >= 0 && gx < WW) ? xb[gy*WW + gx] : 0.f;
    }
    for (int p = tid; p < CC*9*CC; p += 256) {
        int co = p & 15; int tap = (p >> 4) % 9; int ci = p / (9*16);
        w1s[p] = up1_w[(co*CC + ci)*9 + tap];
    }
    __syncthreads();

    // stem: s0 over 18x18 halo region (zero at image OOB = conv padding for step1)
    for (int p = tid; p < 324; p += 256) {
        int ly = p / 18, lx = p % 18;
        int gy = gy0 - 1 + ly, gx = gx0 - 1 + lx;
        bool inb = (gy >= 0 && gy < HH && gx >= 0 && gx < WW);
        #pragma unroll
        for (int c = 0; c < CC; c++) {
            float acc = 0.f;
            if (inb) {
                acc = stem_b[c];
                #pragma unroll
                for (int t = 0; t < 9; t++)
                    acc = fmaf(stem_w[c*9 + t], xs[(ly + t/3)*20 + (lx + t%3)], acc);
                acc = fmaxf(acc, 0.f);
            }
            s0[c][p] = acc;
        }
    }
    __syncthreads();

    // conv3x3 (16->16) + relu
    float y[CC];
    #pragma unroll
    for (int c = 0; c < CC; c++) y[c] = up1_b[c];
    #pragma unroll
    for (int ci = 0; ci < CC; ci++) {
        #pragma unroll
        for (int t = 0; t < 9; t++) {
            float v = s0[ci][(ty + t/3)*18 + (tx + t%3)];
            const float4* w4 = (const float4*)&w1s[(ci*9 + t)*16];
            #pragma unroll
            for (int q = 0; q < 4; q++) {
                float4 wv = w4[q];
                y[4*q+0] = fmaf(wv.x, v, y[4*q+0]);
                y[4*q+1] = fmaf(wv.y, v, y[4*q+1]);
                y[4*q+2] = fmaf(wv.z, v, y[4*q+2]);
                y[4*q+3] = fmaf(wv.w, v, y[4*q+3]);
            }
        }
    }
    #pragma unroll
    for (int c = 0; c < CC; c++) y[c] = fmaxf(y[c], 0.f);

    // delta = up2 @ hidden + b2
    float delta[CC];
    #pragma unroll
    for (int co = 0; co < CC; co++) {
        float acc = up2_b[co];
        #pragma unroll
        for (int ci = 0; ci < CC; ci++) acc = fmaf(up2_w[co*CC + ci], y[ci], acc);
        delta[co] = acc;
    }

    // beta = sigmoid(tau @ state0_center + tau_b); blend
    int ctr = (ty + 1)*18 + (tx + 1);
    float z[CC];
    #pragma unroll
    for (int c = 0; c < CC; c++) {
        float t = tau_b[c];
        #pragma unroll
        for (int ci = 0; ci < CC; ci++) t = fmaf(tau_w[c*CC + ci], s0[ci][ctr], t);
        float beta = 1.f / (1.f + __expf(-t));
        z[c] = fmaf(beta, s0[c][ctr], (1.f - beta) * delta[c]);
    }

    float loss; int bk = vq_argmin(z, loss);
    g_idxA[(b*HH + (gy0 + ty))*WW + (gx0 + tx)] = (unsigned char)bk;
    block_accumulate(loss, bk, 0, red, redu);
}

// ---------------- steps 2..5: pure table-driven update on uint8 index maps ----------------
__global__ __launch_bounds__(256)
void k_step(const float* __restrict__ up1_b, const float* __restrict__ up2_w,
            const float* __restrict__ up2_b, int slot) {
    __shared__ float red[8]; __shared__ unsigned redu[8];
    const unsigned char* ibuf = (slot & 1) ? g_idxA : g_idxB;   // slot 1:A->B, 2:B->A, 3:A->B, 4:B->A
    unsigned char* obuf       = (slot & 1) ? g_idxB : g_idxA;

    int tx = threadIdx.x & 15, ty = threadIdx.x >> 4;
    int gx = blockIdx.x*16 + tx, gy = blockIdx.y*16 + ty, b = blockIdx.z;
    const unsigned char* ib = ibuf + b * HH * WW;

    float y[CC];
    #pragma unroll
    for (int c = 0; c < CC; c++) y[c] = up1_b[c];
    #pragma unroll
    for (int t = 0; t < 9; t++) {
        int ny = gy + t/3 - 1, nx = gx + t%3 - 1;
        if (ny >= 0 && ny < HH && nx >= 0 && nx < WW) {
            int k = ib[ny*WW + nx];
            const float* Mp = &g_M[t*CC*KK + k];
            #pragma unroll
            for (int c = 0; c < CC; c++) y[c] += Mp[c*KK];
        }
    }
    #pragma unroll
    for (int c = 0; c < CC; c++) y[c] = fmaxf(y[c], 0.f);

    float delta[CC];
    #pragma unroll
    for (int co = 0; co < CC; co++) {
        float acc = up2_b[co];
        #pragma unroll
        for (int ci = 0; ci < CC; ci++) acc = fmaf(up2_w[co*CC + ci], y[ci], acc);
        delta[co] = acc;
    }

    int kc = ib[gy*WW + gx];
    float z[CC];
    #pragma unroll
    for (int c = 0; c < CC; c++)
        z[c] = fmaf(g_Q[c*KK + kc], delta[c], g_P[c*KK + kc]);

    float loss; int bk = vq_argmin(z, loss);
    obuf[(b*HH + gy)*WW + gx] = (unsigned char)bk;
    block_accumulate(loss, bk, slot, red, redu);
}

// ---------------- decode: pure 32-entry LUT gather ----------------
__global__ void k_decode(float* __restrict__ out) {
    int i = blockIdx.x * blockDim.x + threadIdx.x;
    if (i < NPIX) out[i] = g_sigD[g_idxA[i]];
}

// ---------------- scalars ----------------
__global__ void k_final(float* __restrict__ out) {
    float vq = 0.f, us = 0.f;
    #pragma unroll
    for (int s = 0; s < NSTEPS; s++) {
        vq += 1.25f * g_sse[s] / (float)NELEM;   // codebook_loss + 0.25*commit == 1.25*mse
        us += (float)__popc(g_used[s]) / (float)KK;
    }
    out[NPIX]     = vq / (float)NSTEPS;
    out[NPIX + 1] = us / (float)NSTEPS;
}

extern "C" void kernel_launch(void* const* d_in, const int* in_sizes, int n_in,
                              void* d_out, int out_size) {
    const float* x      = (const float*)d_in[0];
    const float* stem_w = (const float*)d_in[1];
    const float* stem_b = (const float*)d_in[2];
    const float* up1_w  = (const float*)d_in[3];
    const float* up1_b  = (const float*)d_in[4];
    const float* up2_w  = (const float*)d_in[5];
    const float* up2_b  = (const float*)d_in[6];
    const float* tau_w  = (const float*)d_in[7];
    const float* tau_b  = (const float*)d_in[8];
    const float* cb     = (const float*)d_in[9];
    const float* dec_w  = (const float*)d_in[10];
    const float* dec_b  = (const float*)d_in[11];
    float* out = (float*)d_out;

    k_tables<<<1, 512>>>(up1_w, tau_w, tau_b, cb, dec_w, dec_b);

    dim3 grid(WW/16, HH/16, BATCH), blk(256);
    k_step1<<<grid, blk>>>(x, stem_w, stem_b, up1_w, up1_b, up2_w, up2_b, tau_w, tau_b);
    for (int s = 1; s < NSTEPS; s++)
        k_step<<<grid, blk>>>(up1_b, up2_w, up2_b, s);

    k_decode<<<NPIX/256, 256>>>(out);
    k_final<<<1, 1>>>(out);
}

// round 2
// speedup vs baseline: 1.2566x; 1.2566x over previous
#include <cuda_runtime.h>

#define BATCH 32
#define HH 256
#define WW 256
#define CC 16
#define KK 32
#define NSTEPS 5
#define NPIX (BATCH*HH*WW)           // 2097152
#define NELEM (NPIX*CC)
#define NTILES (NPIX/256)            // 8192

typedef unsigned long long ull;

// ---------------- static device scratch ----------------
__device__ float g_M[9*CC*KK];       // [tap][c][k]
__device__ float g_P[CC*KK];         // beta*cb
__device__ float g_Q[CC*KK];         // 1-beta
__device__ float g_csq[KK];
__device__ float g_sigD[KK];
__device__ float g_sse[NSTEPS];
__device__ unsigned g_used[NSTEPS];
__device__ unsigned char g_idxA[NPIX];
__device__ unsigned char g_idxB[NPIX];

// ---------------- f32x2 helpers ----------------
__device__ __forceinline__ ull pack2f(float lo, float hi) {
    ull d;
    asm("mov.b64 %0,{%1,%2};" : "=l"(d) : "r"(__float_as_uint(lo)), "r"(__float_as_uint(hi)));
    return d;
}
__device__ __forceinline__ void unpack2f(ull v, float& lo, float& hi) {
    unsigned a, b;
    asm("mov.b64 {%0,%1},%2;" : "=r"(a), "=r"(b) : "l"(v));
    lo = __uint_as_float(a); hi = __uint_as_float(b);
}
__device__ __forceinline__ ull fma2(ull a, ull b, ull c) {
    ull d;
    asm("fma.rn.f32x2 %0,%1,%2,%3;" : "=l"(d) : "l"(a), "l"(b), "l"(c));
    return d;
}
__device__ __forceinline__ ull add2(ull a, ull b) {
    ull d;
    asm("add.rn.f32x2 %0,%1,%2;" : "=l"(d) : "l"(a), "l"(b));
    return d;
}

// ---------------- table precompute + accumulator reset ----------------
__global__ void k_tables(const float* __restrict__ up1_w,
                         const float* __restrict__ tau_w, const float* __restrict__ tau_b,
                         const float* __restrict__ cb,
                         const float* __restrict__ dec_w, const float* __restrict__ dec_b) {
    int tid = threadIdx.x;
    for (int e = tid; e < 9*CC*KK; e += blockDim.x) {
        int k = e & 31; int c = (e >> 5) & 15; int tap = e >> 9;
        float acc = 0.f;
        #pragma unroll
        for (int ci = 0; ci < CC; ci++)
            acc = fmaf(up1_w[(c*CC+ci)*9 + tap], cb[k*CC+ci], acc);
        g_M[e] = acc;
    }
    for (int e = tid; e < CC*KK; e += blockDim.x) {
        int k = e & 31; int c = e >> 5;
        float t = tau_b[c];
        #pragma unroll
        for (int ci = 0; ci < CC; ci++)
            t = fmaf(tau_w[c*CC+ci], cb[k*CC+ci], t);
        float beta = 1.f / (1.f + expf(-t));
        g_P[e] = beta * cb[k*CC+c];
        g_Q[e] = 1.f - beta;
    }
    for (int k = tid; k < KK; k += blockDim.x) {
        float s = 0.f, d = dec_b[0];
        #pragma unroll
        for (int c = 0; c < CC; c++) { float v = cb[k*CC+c]; s = fmaf(v, v, s); d = fmaf(dec_w[c], v, d); }
        g_csq[k] = s;
        g_sigD[k] = 1.f / (1.f + expf(-d));
    }
    if (tid < NSTEPS) { g_sse[tid] = 0.f; g_used[tid] = 0u; }
}

// ---------------- block reduce + atomic ----------------
__device__ __forceinline__ void block_accumulate(float loss, unsigned mask, int slot,
                                                 float* red, unsigned* redu) {
    #pragma unroll
    for (int o = 16; o; o >>= 1) loss += __shfl_xor_sync(0xffffffffu, loss, o);
    mask = __reduce_or_sync(0xffffffffu, mask);
    int lane = threadIdx.x & 31, wid = threadIdx.x >> 5;
    if (lane == 0) { red[wid] = loss; redu[wid] = mask; }
    __syncthreads();
    if (threadIdx.x == 0) {
        float s = 0.f; unsigned m = 0u;
        for (int i = 0; i < 8; i++) { s += red[i]; m |= redu[i]; }
        atomicAdd(&g_sse[slot], s);
        atomicOr(&g_used[slot], m);
    }
}

// ---------------- shared VQ: 32 packed accumulators, csq folded in ----------------
// s_cb2n[c*16+j] = (-2cb[2j][c], -2cb[2j+1][c]);  s_csq2[j] = (csq[2j], csq[2j+1])
__device__ __forceinline__ int vq_argmin_s(const float* z, float zsq, float& loss,
                                           const ull* s_cb2n, const ull* s_csq2) {
    ull dot2[16];
    #pragma unroll
    for (int j = 0; j < 16; j++) dot2[j] = s_csq2[j];
    #pragma unroll
    for (int c = 0; c < CC; c++) {
        ull zz = pack2f(z[c], z[c]);
        const ulonglong2* cp = (const ulonglong2*)&s_cb2n[c*16];
        #pragma unroll
        for (int jj = 0; jj < 8; jj++) {
            ulonglong2 w = cp[jj];
            dot2[2*jj]   = fma2(zz, w.x, dot2[2*jj]);
            dot2[2*jj+1] = fma2(zz, w.y, dot2[2*jj+1]);
        }
    }
    float best = 3.4e38f; int bk = 0;
    #pragma unroll
    for (int j = 0; j < 16; j++) {
        float lo, hi; unpack2f(dot2[j], lo, hi);
        if (lo < best) { best = lo; bk = 2*j; }
        if (hi < best) { best = hi; bk = 2*j+1; }
    }
    loss = zsq + best;     // score_k = ||z-cb_k||^2 - zsq
    return bk;
}

// ---------------- fused stem + step 1 ----------------
__global__ __launch_bounds__(256)
void k_step1(const float* __restrict__ x,
             const float* __restrict__ stem_w, const float* __restrict__ stem_b,
             const float* __restrict__ up1_w, const float* __restrict__ up1_b,
             const float* __restrict__ up2_w, const float* __restrict__ up2_b,
             const float* __restrict__ tau_w, const float* __restrict__ tau_b,
             const float* __restrict__ cb) {
    __shared__ float xs[20*20];
    __shared__ float s0[CC][18*18];
    __shared__ ull s_w2[CC*9*8];       // [ci][t][q]: (up1_w[2q][ci][t], up1_w[2q+1][ci][t])
    __shared__ ull s_tw2[CC*8];        // [ci][q]
    __shared__ ull s_u2w2[CC*8];       // [ci][q]
    __shared__ ull s_cb2n[CC*16];
    __shared__ ull s_csq2[16];
    __shared__ ull s_bu1[8], s_bu2[8], s_bt[8];
    __shared__ float red[8]; __shared__ unsigned redu[8];

    int tid = threadIdx.x;
    int tx = tid & 15, tyy = tid >> 4;
    int gx0 = blockIdx.x * 16, gy0 = blockIdx.y * 16, b = blockIdx.z;
    const float* xb = x + b * HH * WW;

    // ---- stage weights ----
    for (int e = tid; e < CC*9*8; e += 256) {
        int q = e & 7; int t = (e >> 3) % 9; int ci = e / 72;
        s_w2[e] = pack2f(up1_w[(2*q*CC + ci)*9 + t], up1_w[((2*q+1)*CC + ci)*9 + t]);
    }
    for (int e = tid; e < CC*8; e += 256) {
        int q = e & 7; int ci = e >> 3;
        s_tw2[e]  = pack2f(tau_w[2*q*CC + ci],  tau_w[(2*q+1)*CC + ci]);
        s_u2w2[e] = pack2f(up2_w[2*q*CC + ci],  up2_w[(2*q+1)*CC + ci]);
    }
    for (int e = tid; e < CC*16; e += 256) {
        int j = e & 15; int c = e >> 4;
        s_cb2n[e] = pack2f(-2.f*cb[2*j*CC + c], -2.f*cb[(2*j+1)*CC + c]);
    }
    if (tid < 16) s_csq2[tid] = pack2f(g_csq[2*tid], g_csq[2*tid+1]);
    if (tid < 8) {
        s_bu1[tid] = pack2f(up1_b[2*tid], up1_b[2*tid+1]);
        s_bu2[tid] = pack2f(up2_b[2*tid], up2_b[2*tid+1]);
        s_bt[tid]  = pack2f(tau_b[2*tid], tau_b[2*tid+1]);
    }
    for (int p = tid; p < 400; p += 256) {
        int iy = p / 20, ix = p % 20;
        int gy = gy0 - 2 + iy, gx = gx0 - 2 + ix;
        xs[p] = (gy >= 0 && gy < HH && gx >= 0 && gx < WW) ? xb[gy*WW + gx] : 0.f;
    }
    __syncthreads();

    // ---- stem over 18x18 halo ----
    for (int p = tid; p < 324; p += 256) {
        int ly = p / 18, lx = p % 18;
        int gy = gy0 - 1 + ly, gx = gx0 - 1 + lx;
        bool inb = (gy >= 0 && gy < HH && gx >= 0 && gx < WW);
        #pragma unroll
        for (int c = 0; c < CC; c++) {
            float acc = 0.f;
            if (inb) {
                acc = stem_b[c];
                #pragma unroll
                for (int t = 0; t < 9; t++)
                    acc = fmaf(stem_w[c*9 + t], xs[(ly + t/3)*20 + (lx + t%3)], acc);
                acc = fmaxf(acc, 0.f);
            }
            s0[c][p] = acc;
        }
    }
    __syncthreads();

    // ---- conv3x3 16->16 (f32x2 over output-channel pairs) ----
    ull y2[8];
    #pragma unroll
    for (int q = 0; q < 8; q++) y2[q] = s_bu1[q];
    #pragma unroll
    for (int ci = 0; ci < CC; ci++) {
        #pragma unroll
        for (int t = 0; t < 9; t++) {
            float v = s0[ci][(tyy + t/3)*18 + (tx + t%3)];
            ull vv = pack2f(v, v);
            const ulonglong2* wp = (const ulonglong2*)&s_w2[(ci*9 + t)*8];
            #pragma unroll
            for (int qq = 0; qq < 4; qq++) {
                ulonglong2 w = wp[qq];
                y2[2*qq]   = fma2(vv, w.x, y2[2*qq]);
                y2[2*qq+1] = fma2(vv, w.y, y2[2*qq+1]);
            }
        }
    }
    float yv[CC];
    #pragma unroll
    for (int q = 0; q < 8; q++) {
        float lo, hi; unpack2f(y2[q], lo, hi);
        yv[2*q] = fmaxf(lo, 0.f); yv[2*q+1] = fmaxf(hi, 0.f);
    }

    // ---- delta = up2 @ yv ----
    ull d2[8];
    #pragma unroll
    for (int q = 0; q < 8; q++) d2[q] = s_bu2[q];
    #pragma unroll
    for (int ci = 0; ci < CC; ci++) {
        ull vv = pack2f(yv[ci], yv[ci]);
        const ulonglong2* wp = (const ulonglong2*)&s_u2w2[ci*8];
        #pragma unroll
        for (int qq = 0; qq < 4; qq++) {
            ulonglong2 w = wp[qq];
            d2[2*qq]   = fma2(vv, w.x, d2[2*qq]);
            d2[2*qq+1] = fma2(vv, w.y, d2[2*qq+1]);
        }
    }

    // ---- tau: t = tau_w @ s0_center + tau_b ----
    int ctr = (tyy + 1)*18 + (tx + 1);
    float s0c[CC];
    #pragma unroll
    for (int c = 0; c < CC; c++) s0c[c] = s0[c][ctr];
    ull t2[8];
    #pragma unroll
    for (int q = 0; q < 8; q++) t2[q] = s_bt[q];
    #pragma unroll
    for (int ci = 0; ci < CC; ci++) {
        ull vv = pack2f(s0c[ci], s0c[ci]);
        const ulonglong2* wp = (const ulonglong2*)&s_tw2[ci*8];
        #pragma unroll
        for (int qq = 0; qq < 4; qq++) {
            ulonglong2 w = wp[qq];
            t2[2*qq]   = fma2(vv, w.x, t2[2*qq]);
            t2[2*qq+1] = fma2(vv, w.y, t2[2*qq+1]);
        }
    }

    float z[CC]; float zsq = 0.f;
    #pragma unroll
    for (int q = 0; q < 8; q++) {
        float tlo, thi; unpack2f(t2[q], tlo, thi);
        float dlo, dhi; unpack2f(d2[q], dlo, dhi);
        float blo = 1.f / (1.f + __expf(-tlo));
        float bhi = 1.f / (1.f + __expf(-thi));
        float zlo = fmaf(blo, s0c[2*q],   (1.f - blo) * dlo);
        float zhi = fmaf(bhi, s0c[2*q+1], (1.f - bhi) * dhi);
        z[2*q] = zlo; z[2*q+1] = zhi;
        zsq = fmaf(zlo, zlo, zsq); zsq = fmaf(zhi, zhi, zsq);
    }

    float loss; int bk = vq_argmin_s(z, zsq, loss, s_cb2n, s_csq2);
    g_idxA[(b*HH + gy0 + tyy)*WW + gx0 + tx] = (unsigned char)bk;
    block_accumulate(loss, 1u << bk, 0, red, redu);
}

// ---------------- steps 2..5: persistent, table-driven, smem everything ----------------
__global__ __launch_bounds__(256)
void k_step(const float* __restrict__ up1_b, const float* __restrict__ up2_w,
            const float* __restrict__ up2_b, const float* __restrict__ cb, int slot) {
    __shared__ ull s_M2[9*8*33];        // [t][q][k], sentinel k=32 -> 0
    __shared__ ull s_P2[8*32], s_Q2[8*32];
    __shared__ ull s_cb2n[CC*16];
    __shared__ ull s_csq2[16];
    __shared__ ull s_bu1[8], s_bu2[8];
    __shared__ ull s_u2w2[CC*8];
    __shared__ unsigned char s_idx[18*18];
    __shared__ float red[8]; __shared__ unsigned redu[8];

    int tid = threadIdx.x;
    for (int e = tid; e < 9*8*33; e += 256) {
        int k = e % 33; int q = (e/33) & 7; int t = e/(33*8);
        float lo = 0.f, hi = 0.f;
        if (k < 32) { lo = g_M[(t*CC + 2*q)*KK + k]; hi = g_M[(t*CC + 2*q+1)*KK + k]; }
        s_M2[e] = pack2f(lo, hi);
    }
    for (int e = tid; e < 8*32; e += 256) {
        int k = e & 31; int q = e >> 5;
        s_P2[e] = pack2f(g_P[2*q*KK + k], g_P[(2*q+1)*KK + k]);
        s_Q2[e] = pack2f(g_Q[2*q*KK + k], g_Q[(2*q+1)*KK + k]);
    }
    for (int e = tid; e < CC*16; e += 256) {
        int j = e & 15; int c = e >> 4;
        s_cb2n[e] = pack2f(-2.f*cb[2*j*CC + c], -2.f*cb[(2*j+1)*CC + c]);
    }
    if (tid < 16) s_csq2[tid] = pack2f(g_csq[2*tid], g_csq[2*tid+1]);
    if (tid < 8) {
        s_bu1[tid] = pack2f(up1_b[2*tid], up1_b[2*tid+1]);
        s_bu2[tid] = pack2f(up2_b[2*tid], up2_b[2*tid+1]);
    }
    for (int e = tid; e < CC*8; e += 256) {
        int q = e & 7; int ci = e >> 3;
        s_u2w2[e] = pack2f(up2_w[2*q*CC + ci], up2_w[(2*q+1)*CC + ci]);
    }

    const unsigned char* ibuf = (slot & 1) ? g_idxA : g_idxB;
    unsigned char* obuf       = (slot & 1) ? g_idxB : g_idxA;

    int tx = tid & 15, tyy = tid >> 4;
    float loc_loss = 0.f; unsigned loc_mask = 0u;

    for (int tile = blockIdx.x; tile < NTILES; tile += gridDim.x) {
        int b = tile >> 8; int rem = tile & 255;
        int gy0 = (rem >> 4) << 4, gx0 = (rem & 15) << 4;
        const unsigned char* ib = ibuf + b * HH * WW;

        __syncthreads();
        for (int p = tid; p < 324; p += 256) {
            int iy = p / 18, ix = p % 18;
            int gy = gy0 - 1 + iy, gx = gx0 - 1 + ix;
            s_idx[p] = (gy >= 0 && gy < HH && gx >= 0 && gx < WW) ? ib[gy*WW + gx] : 32;
        }
        __syncthreads();

        // conv via table adds
        ull y2[8];
        #pragma unroll
        for (int q = 0; q < 8; q++) y2[q] = s_bu1[q];
        #pragma unroll
        for (int t = 0; t < 9; t++) {
            int kt = s_idx[(tyy + t/3)*18 + tx + t%3];
            const ull* Mp = &s_M2[t*8*33 + kt];
            #pragma unroll
            for (int q = 0; q < 8; q++) y2[q] = add2(y2[q], Mp[q*33]);
        }
        float yv[CC];
        #pragma unroll
        for (int q = 0; q < 8; q++) {
            float lo, hi; unpack2f(y2[q], lo, hi);
            yv[2*q] = fmaxf(lo, 0.f); yv[2*q+1] = fmaxf(hi, 0.f);
        }

        // delta
        ull d2[8];
        #pragma unroll
        for (int q = 0; q < 8; q++) d2[q] = s_bu2[q];
        #pragma unroll
        for (int ci = 0; ci < CC; ci++) {
            ull vv = pack2f(yv[ci], yv[ci]);
            const ulonglong2* wp = (const ulonglong2*)&s_u2w2[ci*8];
            #pragma unroll
            for (int qq = 0; qq < 4; qq++) {
                ulonglong2 w = wp[qq];
                d2[2*qq]   = fma2(vv, w.x, d2[2*qq]);
                d2[2*qq+1] = fma2(vv, w.y, d2[2*qq+1]);
            }
        }

        // blend via P/Q tables on center code
        int kc = s_idx[(tyy + 1)*18 + tx + 1];
        float z[CC]; float zsq = 0.f;
        #pragma unroll
        for (int q = 0; q < 8; q++) {
            ull zz = fma2(s_Q2[q*32 + kc], d2[q], s_P2[q*32 + kc]);
            float lo, hi; unpack2f(zz, lo, hi);
            z[2*q] = lo; z[2*q+1] = hi;
            zsq = fmaf(lo, lo, zsq); zsq = fmaf(hi, hi, zsq);
        }

        float loss; int bk = vq_argmin_s(z, zsq, loss, s_cb2n, s_csq2);
        obuf[(b*HH + gy0 + tyy)*WW + gx0 + tx] = (unsigned char)bk;
        loc_loss += loss;
        loc_mask |= 1u << bk;
    }
    __syncthreads();
    block_accumulate(loc_loss, loc_mask, slot, red, redu);
}

// ---------------- decode + scalars ----------------
__global__ void k_decode(float* __restrict__ out) {
    int i = blockIdx.x * blockDim.x + threadIdx.x;
    if (i < NPIX) out[i] = g_sigD[g_idxA[i]];
}

__global__ void k_final(float* __restrict__ out) {
    float vq = 0.f, us = 0.f;
    #pragma unroll
    for (int s = 0; s < NSTEPS; s++) {
        vq += 1.25f * g_sse[s] / (float)NELEM;
        us += (float)__popc(g_used[s]) / (float)KK;
    }
    out[NPIX]     = vq / (float)NSTEPS;
    out[NPIX + 1] = us / (float)NSTEPS;
}

extern "C" void kernel_launch(void* const* d_in, const int* in_sizes, int n_in,
                              void* d_out, int out_size) {
    const float* x      = (const float*)d_in[0];
    const float* stem_w = (const float*)d_in[1];
    const float* stem_b = (const float*)d_in[2];
    const float* up1_w  = (const float*)d_in[3];
    const float* up1_b  = (const float*)d_in[4];
    const float* up2_w  = (const float*)d_in[5];
    const float* up2_b  = (const float*)d_in[6];
    const float* tau_w  = (const float*)d_in[7];
    const float* tau_b  = (const float*)d_in[8];
    const float* cb     = (const float*)d_in[9];
    const float* dec_w  = (const float*)d_in[10];
    const float* dec_b  = (const float*)d_in[11];
    float* out = (float*)d_out;

    k_tables<<<1, 512>>>(up1_w, tau_w, tau_b, cb, dec_w, dec_b);

    dim3 grid1(WW/16, HH/16, BATCH), blk(256);
    k_step1<<<grid1, blk>>>(x, stem_w, stem_b, up1_w, up1_b, up2_w, up2_b, tau_w, tau_b, cb);
    for (int s = 1; s < NSTEPS; s++)
        k_step<<<592, blk>>>(up1_b, up2_w, up2_b, cb, s);

    k_decode<<<NPIX/256, 256>>>(out);
    k_final<<<1, 1>>>(out);
}

// round 3
// speedup vs baseline: 1.5527x; 1.2356x over previous
#include <cuda_runtime.h>

#define BATCH 32
#define HH 256
#define WW 256
#define CC 16
#define KK 32
#define NSTEPS 5
#define NPIX (BATCH*HH*WW)           // 2097152
#define NELEM (NPIX*CC)
#define NT2 (NPIX/512)               // 4096 tiles of 16x32

typedef unsigned long long ull;

// ---------------- static device scratch ----------------
__device__ float g_M[9*CC*KK];       // [tap][c][k]
__device__ float g_P[CC*KK];         // beta*cb
__device__ float g_Q[CC*KK];         // 1-beta
__device__ float g_csq[KK];
__device__ float g_sigD[KK];
__device__ float g_sse[NSTEPS];
__device__ unsigned g_used[NSTEPS];
__device__ unsigned char g_idxA[NPIX];
__device__ unsigned char g_idxB[NPIX];

// ---------------- f32x2 helpers ----------------
__device__ __forceinline__ ull pack2f(float lo, float hi) {
    ull d;
    asm("mov.b64 %0,{%1,%2};" : "=l"(d) : "r"(__float_as_uint(lo)), "r"(__float_as_uint(hi)));
    return d;
}
__device__ __forceinline__ void unpack2f(ull v, float& lo, float& hi) {
    unsigned a, b;
    asm("mov.b64 {%0,%1},%2;" : "=r"(a), "=r"(b) : "l"(v));
    lo = __uint_as_float(a); hi = __uint_as_float(b);
}
__device__ __forceinline__ ull fma2(ull a, ull b, ull c) {
    ull d;
    asm("fma.rn.f32x2 %0,%1,%2,%3;" : "=l"(d) : "l"(a), "l"(b), "l"(c));
    return d;
}
__device__ __forceinline__ ull add2(ull a, ull b) {
    ull d;
    asm("add.rn.f32x2 %0,%1,%2;" : "=l"(d) : "l"(a), "l"(b));
    return d;
}

// ---------------- table precompute ----------------
__global__ void k_tables(const float* __restrict__ up1_w,
                         const float* __restrict__ tau_w, const float* __restrict__ tau_b,
                         const float* __restrict__ cb,
                         const float* __restrict__ dec_w, const float* __restrict__ dec_b) {
    int tid = threadIdx.x;
    for (int e = tid; e < 9*CC*KK; e += blockDim.x) {
        int k = e & 31; int c = (e >> 5) & 15; int tap = e >> 9;
        float acc = 0.f;
        #pragma unroll
        for (int ci = 0; ci < CC; ci++)
            acc = fmaf(up1_w[(c*CC+ci)*9 + tap], cb[k*CC+ci], acc);
        g_M[e] = acc;
    }
    for (int e = tid; e < CC*KK; e += blockDim.x) {
        int k = e & 31; int c = e >> 5;
        float t = tau_b[c];
        #pragma unroll
        for (int ci = 0; ci < CC; ci++)
            t = fmaf(tau_w[c*CC+ci], cb[k*CC+ci], t);
        float beta = 1.f / (1.f + expf(-t));
        g_P[e] = beta * cb[k*CC+c];
        g_Q[e] = 1.f - beta;
    }
    for (int k = tid; k < KK; k += blockDim.x) {
        float s = 0.f, d = dec_b[0];
        #pragma unroll
        for (int c = 0; c < CC; c++) { float v = cb[k*CC+c]; s = fmaf(v, v, s); d = fmaf(dec_w[c], v, d); }
        g_csq[k] = s;
        g_sigD[k] = 1.f / (1.f + expf(-d));
    }
    if (tid < NSTEPS) { g_sse[tid] = 0.f; g_used[tid] = 0u; }
}

// ---------------- block reduce + atomic ----------------
__device__ __forceinline__ void block_accumulate(float loss, unsigned mask, int slot,
                                                 float* red, unsigned* redu) {
    #pragma unroll
    for (int o = 16; o; o >>= 1) loss += __shfl_xor_sync(0xffffffffu, loss, o);
    mask = __reduce_or_sync(0xffffffffu, mask);
    int lane = threadIdx.x & 31, wid = threadIdx.x >> 5;
    if (lane == 0) { red[wid] = loss; redu[wid] = mask; }
    __syncthreads();
    if (threadIdx.x == 0) {
        float s = 0.f; unsigned m = 0u;
        int nw = blockDim.x >> 5;
        for (int i = 0; i < nw; i++) { s += red[i]; m |= redu[i]; }
        atomicAdd(&g_sse[slot], s);
        atomicOr(&g_used[slot], m);
    }
}

// ---------------- dual-pixel VQ: codebook loads shared between 2 pixels ----------------
__device__ __forceinline__ void vq2(const ull* z2a, const ull* z2b, float zsqa, float zsqb,
                                    const ull* s_cb2n, const ull* s_csq2,
                                    int& bka, int& bkb, float& la, float& lb) {
    ull da[16], db[16];
    #pragma unroll
    for (int j = 0; j < 16; j++) { ull c0 = s_csq2[j]; da[j] = c0; db[j] = c0; }
    #pragma unroll
    for (int q = 0; q < 8; q++) {
        float a0, a1, b0, b1;
        unpack2f(z2a[q], a0, a1); unpack2f(z2b[q], b0, b1);
        ull za0 = pack2f(a0, a0), za1 = pack2f(a1, a1);
        ull zb0 = pack2f(b0, b0), zb1 = pack2f(b1, b1);
        const ulonglong2* cp0 = (const ulonglong2*)&s_cb2n[(2*q)*16];
        const ulonglong2* cp1 = (const ulonglong2*)&s_cb2n[(2*q+1)*16];
        #pragma unroll
        for (int jj = 0; jj < 8; jj++) {
            ulonglong2 w0 = cp0[jj], w1 = cp1[jj];
            da[2*jj]   = fma2(za0, w0.x, da[2*jj]);   da[2*jj+1] = fma2(za0, w0.y, da[2*jj+1]);
            db[2*jj]   = fma2(zb0, w0.x, db[2*jj]);   db[2*jj+1] = fma2(zb0, w0.y, db[2*jj+1]);
            da[2*jj]   = fma2(za1, w1.x, da[2*jj]);   da[2*jj+1] = fma2(za1, w1.y, da[2*jj+1]);
            db[2*jj]   = fma2(zb1, w1.x, db[2*jj]);   db[2*jj+1] = fma2(zb1, w1.y, db[2*jj+1]);
        }
    }
    float besta = 3.4e38f, bestb = 3.4e38f; bka = 0; bkb = 0;
    #pragma unroll
    for (int j = 0; j < 16; j++) {
        float lo, hi;
        unpack2f(da[j], lo, hi);
        if (lo < besta) { besta = lo; bka = 2*j; }
        if (hi < besta) { besta = hi; bka = 2*j+1; }
        unpack2f(db[j], lo, hi);
        if (lo < bestb) { bestb = lo; bkb = 2*j; }
        if (hi < bestb) { bestb = hi; bkb = 2*j+1; }
    }
    la = zsqa + besta;
    lb = zsqb + bestb;
}

// ---------------- fused stem + step 1: 16x16 tile, 128 threads, 2 px/thread ----------------
__global__ __launch_bounds__(128)
void k_step1(const float* __restrict__ x,
             const float* __restrict__ stem_w, const float* __restrict__ stem_b,
             const float* __restrict__ up1_w, const float* __restrict__ up1_b,
             const float* __restrict__ up2_w, const float* __restrict__ up2_b,
             const float* __restrict__ tau_w, const float* __restrict__ tau_b,
             const float* __restrict__ cb) {
    __shared__ float xs[20*20];
    __shared__ float s0[CC][18*18];
    __shared__ ull s_w2[CC*9*8];
    __shared__ ull s_tw2[CC*8], s_u2w2[CC*8];
    __shared__ ull s_cb2n[CC*16];
    __shared__ ull s_csq2[16];
    __shared__ ull s_bu1[8], s_bu2[8], s_bt[8];
    __shared__ float red[4]; __shared__ unsigned redu[4];

    int tid = threadIdx.x;
    int tx = tid & 15, ty = tid >> 4;      // ty 0..7, handles rows 2ty, 2ty+1
    int gx0 = blockIdx.x * 16, gy0 = blockIdx.y * 16, b = blockIdx.z;
    const float* xb = x + b * HH * WW;

    for (int e = tid; e < CC*9*8; e += 128) {
        int q = e & 7; int t = (e >> 3) % 9; int ci = e / 72;
        s_w2[e] = pack2f(up1_w[(2*q*CC + ci)*9 + t], up1_w[((2*q+1)*CC + ci)*9 + t]);
    }
    for (int e = tid; e < CC*8; e += 128) {
        int q = e & 7; int ci = e >> 3;
        s_tw2[e]  = pack2f(tau_w[2*q*CC + ci],  tau_w[(2*q+1)*CC + ci]);
        s_u2w2[e] = pack2f(up2_w[2*q*CC + ci],  up2_w[(2*q+1)*CC + ci]);
    }
    for (int e = tid; e < CC*16; e += 128) {
        int j = e & 15; int c = e >> 4;
        s_cb2n[e] = pack2f(-2.f*cb[2*j*CC + c], -2.f*cb[(2*j+1)*CC + c]);
    }
    if (tid < 16) s_csq2[tid] = pack2f(g_csq[2*tid], g_csq[2*tid+1]);
    if (tid < 8) {
        s_bu1[tid] = pack2f(up1_b[2*tid], up1_b[2*tid+1]);
        s_bu2[tid] = pack2f(up2_b[2*tid], up2_b[2*tid+1]);
        s_bt[tid]  = pack2f(tau_b[2*tid], tau_b[2*tid+1]);
    }
    for (int p = tid; p < 400; p += 128) {
        int iy = p / 20, ix = p % 20;
        int gy = gy0 - 2 + iy, gx = gx0 - 2 + ix;
        xs[p] = (gy >= 0 && gy < HH && gx >= 0 && gx < WW) ? xb[gy*WW + gx] : 0.f;
    }
    __syncthreads();

    // stem over 18x18 halo
    for (int p = tid; p < 324; p += 128) {
        int ly = p / 18, lx = p % 18;
        int gy = gy0 - 1 + ly, gx = gx0 - 1 + lx;
        bool inb = (gy >= 0 && gy < HH && gx >= 0 && gx < WW);
        #pragma unroll
        for (int c = 0; c < CC; c++) {
            float acc = 0.f;
            if (inb) {
                acc = stem_b[c];
                #pragma unroll
                for (int t = 0; t < 9; t++)
                    acc = fmaf(stem_w[c*9 + t], xs[(ly + t/3)*20 + (lx + t%3)], acc);
                acc = fmaxf(acc, 0.f);
            }
            s0[c][p] = acc;
        }
    }
    __syncthreads();

    // ---- conv3x3 16->16, 2 pixels/thread, weights + window rows shared ----
    ull y2a[8], y2b[8];
    #pragma unroll
    for (int q = 0; q < 8; q++) { y2a[q] = s_bu1[q]; y2b[q] = s_bu1[q]; }
    #pragma unroll 4
    for (int ci = 0; ci < CC; ci++) {
        const float* s0p = &s0[ci][0];
        #pragma unroll
        for (int tc = 0; tc < 3; tc++) {
            float v0 = s0p[(2*ty+0)*18 + tx + tc];
            float v1 = s0p[(2*ty+1)*18 + tx + tc];
            float v2 = s0p[(2*ty+2)*18 + tx + tc];
            float v3 = s0p[(2*ty+3)*18 + tx + tc];
            #pragma unroll
            for (int tr = 0; tr < 3; tr++) {
                int t = tr*3 + tc;
                float va = (tr == 0) ? v0 : ((tr == 1) ? v1 : v2);
                float vb = (tr == 0) ? v1 : ((tr == 1) ? v2 : v3);
                ull vva = pack2f(va, va), vvb = pack2f(vb, vb);
                const ulonglong2* wp = (const ulonglong2*)&s_w2[(ci*9 + t)*8];
                #pragma unroll
                for (int qq = 0; qq < 4; qq++) {
                    ulonglong2 w = wp[qq];
                    y2a[2*qq]   = fma2(vva, w.x, y2a[2*qq]);
                    y2a[2*qq+1] = fma2(vva, w.y, y2a[2*qq+1]);
                    y2b[2*qq]   = fma2(vvb, w.x, y2b[2*qq]);
                    y2b[2*qq+1] = fma2(vvb, w.y, y2b[2*qq+1]);
                }
            }
        }
    }
    float yva[CC], yvb[CC];
    #pragma unroll
    for (int q = 0; q < 8; q++) {
        float lo, hi;
        unpack2f(y2a[q], lo, hi); yva[2*q] = fmaxf(lo, 0.f); yva[2*q+1] = fmaxf(hi, 0.f);
        unpack2f(y2b[q], lo, hi); yvb[2*q] = fmaxf(lo, 0.f); yvb[2*q+1] = fmaxf(hi, 0.f);
    }

    // ---- delta, weights shared ----
    ull d2a[8], d2b[8];
    #pragma unroll
    for (int q = 0; q < 8; q++) { d2a[q] = s_bu2[q]; d2b[q] = s_bu2[q]; }
    #pragma unroll 4
    for (int ci = 0; ci < CC; ci++) {
        ull va = pack2f(yva[ci], yva[ci]), vb = pack2f(yvb[ci], yvb[ci]);
        const ulonglong2* wp = (const ulonglong2*)&s_u2w2[ci*8];
        #pragma unroll
        for (int qq = 0; qq < 4; qq++) {
            ulonglong2 w = wp[qq];
            d2a[2*qq]   = fma2(va, w.x, d2a[2*qq]);
            d2a[2*qq+1] = fma2(va, w.y, d2a[2*qq+1]);
            d2b[2*qq]   = fma2(vb, w.x, d2b[2*qq]);
            d2b[2*qq+1] = fma2(vb, w.y, d2b[2*qq+1]);
        }
    }

    // ---- tau, weights shared ----
    float sca[CC], scb[CC];
    #pragma unroll
    for (int c = 0; c < CC; c++) {
        sca[c] = s0[c][(2*ty+1)*18 + tx + 1];
        scb[c] = s0[c][(2*ty+2)*18 + tx + 1];
    }
    ull t2a[8], t2b[8];
    #pragma unroll
    for (int q = 0; q < 8; q++) { t2a[q] = s_bt[q]; t2b[q] = s_bt[q]; }
    #pragma unroll 4
    for (int ci = 0; ci < CC; ci++) {
        ull va = pack2f(sca[ci], sca[ci]), vb = pack2f(scb[ci], scb[ci]);
        const ulonglong2* wp = (const ulonglong2*)&s_tw2[ci*8];
        #pragma unroll
        for (int qq = 0; qq < 4; qq++) {
            ulonglong2 w = wp[qq];
            t2a[2*qq]   = fma2(va, w.x, t2a[2*qq]);
            t2a[2*qq+1] = fma2(va, w.y, t2a[2*qq+1]);
            t2b[2*qq]   = fma2(vb, w.x, t2b[2*qq]);
            t2b[2*qq+1] = fma2(vb, w.y, t2b[2*qq+1]);
        }
    }

    // ---- blend + zsq ----
    ull z2a[8], z2b[8]; float zsqa = 0.f, zsqb = 0.f;
    #pragma unroll
    for (int q = 0; q < 8; q++) {
        float tlo, thi, dlo, dhi, zlo, zhi;
        unpack2f(t2a[q], tlo, thi); unpack2f(d2a[q], dlo, dhi);
        {
            float blo = 1.f / (1.f + __expf(-tlo));
            float bhi = 1.f / (1.f + __expf(-thi));
            zlo = fmaf(blo, sca[2*q],   (1.f - blo) * dlo);
            zhi = fmaf(bhi, sca[2*q+1], (1.f - bhi) * dhi);
            zsqa = fmaf(zlo, zlo, zsqa); zsqa = fmaf(zhi, zhi, zsqa);
            z2a[q] = pack2f(zlo, zhi);
        }
        unpack2f(t2b[q], tlo, thi); unpack2f(d2b[q], dlo, dhi);
        {
            float blo = 1.f / (1.f + __expf(-tlo));
            float bhi = 1.f / (1.f + __expf(-thi));
            zlo = fmaf(blo, scb[2*q],   (1.f - blo) * dlo);
            zhi = fmaf(bhi, scb[2*q+1], (1.f - bhi) * dhi);
            zsqb = fmaf(zlo, zlo, zsqb); zsqb = fmaf(zhi, zhi, zsqb);
            z2b[q] = pack2f(zlo, zhi);
        }
    }

    int bka, bkb; float la, lb;
    vq2(z2a, z2b, zsqa, zsqb, s_cb2n, s_csq2, bka, bkb, la, lb);

    int gya = gy0 + 2*ty;
    g_idxA[(b*HH + gya    )*WW + gx0 + tx] = (unsigned char)bka;
    g_idxA[(b*HH + gya + 1)*WW + gx0 + tx] = (unsigned char)bkb;
    block_accumulate(la + lb, (1u << bka) | (1u << bkb), 0, red, redu);
}

// ---------------- steps 2..5: persistent, 16x32 tile, 256 threads, 2 px/thread ----------------
__global__ __launch_bounds__(256)
void k_step(const float* __restrict__ up1_b, const float* __restrict__ up2_w,
            const float* __restrict__ up2_b, const float* __restrict__ cb, int slot) {
    __shared__ ull s_M2[9*8*33];        // [t][q][k], sentinel k=32 -> 0
    __shared__ ull s_P2[8*32], s_Q2[8*32];
    __shared__ ull s_cb2n[CC*16];
    __shared__ ull s_csq2[16];
    __shared__ ull s_bu1[8], s_bu2[8];
    __shared__ ull s_u2w2[CC*8];
    __shared__ unsigned char s_idx[34*18];
    __shared__ float red[8]; __shared__ unsigned redu[8];

    int tid = threadIdx.x;
    for (int e = tid; e < 9*8*33; e += 256) {
        int k = e % 33; int q = (e/33) & 7; int t = e/(33*8);
        float lo = 0.f, hi = 0.f;
        if (k < 32) { lo = g_M[(t*CC + 2*q)*KK + k]; hi = g_M[(t*CC + 2*q+1)*KK + k]; }
        s_M2[e] = pack2f(lo, hi);
    }
    for (int e = tid; e < 8*32; e += 256) {
        int k = e & 31; int q = e >> 5;
        s_P2[e] = pack2f(g_P[2*q*KK + k], g_P[(2*q+1)*KK + k]);
        s_Q2[e] = pack2f(g_Q[2*q*KK + k], g_Q[(2*q+1)*KK + k]);
    }
    for (int e = tid; e < CC*16; e += 256) {
        int j = e & 15; int c = e >> 4;
        s_cb2n[e] = pack2f(-2.f*cb[2*j*CC + c], -2.f*cb[(2*j+1)*CC + c]);
    }
    if (tid < 16) s_csq2[tid] = pack2f(g_csq[2*tid], g_csq[2*tid+1]);
    if (tid < 8) {
        s_bu1[tid] = pack2f(up1_b[2*tid], up1_b[2*tid+1]);
        s_bu2[tid] = pack2f(up2_b[2*tid], up2_b[2*tid+1]);
    }
    for (int e = tid; e < CC*8; e += 256) {
        int q = e & 7; int ci = e >> 3;
        s_u2w2[e] = pack2f(up2_w[2*q*CC + ci], up2_w[(2*q+1)*CC + ci]);
    }

    const unsigned char* ibuf = (slot & 1) ? g_idxA : g_idxB;
    unsigned char* obuf       = (slot & 1) ? g_idxB : g_idxA;

    int tx = tid & 15, ty = tid >> 4;   // ty 0..15, rows 2ty, 2ty+1 of 32-row tile
    float loc_loss = 0.f; unsigned loc_mask = 0u;

    for (int tile = blockIdx.x; tile < NT2; tile += gridDim.x) {
        int b = tile >> 7; int rem = tile & 127;
        int gy0 = (rem >> 4) << 5, gx0 = (rem & 15) << 4;
        const unsigned char* ib = ibuf + b * HH * WW;

        __syncthreads();
        for (int p = tid; p < 34*18; p += 256) {
            int iy = p / 18, ix = p % 18;
            int gy = gy0 - 1 + iy, gx = gx0 - 1 + ix;
            s_idx[p] = (gy >= 0 && gy < HH && gx >= 0 && gx < WW) ? ib[gy*WW + gx] : 32;
        }
        __syncthreads();

        // conv via table adds; idx rows shared between the 2 pixels
        ull y2a[8], y2b[8];
        #pragma unroll
        for (int q = 0; q < 8; q++) { y2a[q] = s_bu1[q]; y2b[q] = s_bu1[q]; }
        #pragma unroll
        for (int tc = 0; tc < 3; tc++) {
            int i0 = s_idx[(2*ty+0)*18 + tx + tc];
            int i1 = s_idx[(2*ty+1)*18 + tx + tc];
            int i2 = s_idx[(2*ty+2)*18 + tx + tc];
            int i3 = s_idx[(2*ty+3)*18 + tx + tc];
            #pragma unroll
            for (int tr = 0; tr < 3; tr++) {
                int t = tr*3 + tc;
                int ka = (tr == 0) ? i0 : ((tr == 1) ? i1 : i2);
                int kb = (tr == 0) ? i1 : ((tr == 1) ? i2 : i3);
                const ull* Ma = &s_M2[t*8*33 + ka];
                const ull* Mb = &s_M2[t*8*33 + kb];
                #pragma unroll
                for (int q = 0; q < 8; q++) {
                    y2a[q] = add2(y2a[q], Ma[q*33]);
                    y2b[q] = add2(y2b[q], Mb[q*33]);
                }
            }
        }
        float yva[CC], yvb[CC];
        #pragma unroll
        for (int q = 0; q < 8; q++) {
            float lo, hi;
            unpack2f(y2a[q], lo, hi); yva[2*q] = fmaxf(lo, 0.f); yva[2*q+1] = fmaxf(hi, 0.f);
            unpack2f(y2b[q], lo, hi); yvb[2*q] = fmaxf(lo, 0.f); yvb[2*q+1] = fmaxf(hi, 0.f);
        }

        // delta, weights shared
        ull d2a[8], d2b[8];
        #pragma unroll
        for (int q = 0; q < 8; q++) { d2a[q] = s_bu2[q]; d2b[q] = s_bu2[q]; }
        #pragma unroll 4
        for (int ci = 0; ci < CC; ci++) {
            ull va = pack2f(yva[ci], yva[ci]), vb = pack2f(yvb[ci], yvb[ci]);
            const ulonglong2* wp = (const ulonglong2*)&s_u2w2[ci*8];
            #pragma unroll
            for (int qq = 0; qq < 4; qq++) {
                ulonglong2 w = wp[qq];
                d2a[2*qq]   = fma2(va, w.x, d2a[2*qq]);
                d2a[2*qq+1] = fma2(va, w.y, d2a[2*qq+1]);
                d2b[2*qq]   = fma2(vb, w.x, d2b[2*qq]);
                d2b[2*qq+1] = fma2(vb, w.y, d2b[2*qq+1]);
            }
        }

        // blend via P/Q tables on center codes
        int kca = s_idx[(2*ty+1)*18 + tx + 1];
        int kcb = s_idx[(2*ty+2)*18 + tx + 1];
        ull z2a[8], z2b[8]; float zsqa = 0.f, zsqb = 0.f;
        #pragma unroll
        for (int q = 0; q < 8; q++) {
            ull za = fma2(s_Q2[q*32 + kca], d2a[q], s_P2[q*32 + kca]);
            ull zb = fma2(s_Q2[q*32 + kcb], d2b[q], s_P2[q*32 + kcb]);
            float lo, hi;
            unpack2f(za, lo, hi); zsqa = fmaf(lo, lo, zsqa); zsqa = fmaf(hi, hi, zsqa);
            unpack2f(zb, lo, hi); zsqb = fmaf(lo, lo, zsqb); zsqb = fmaf(hi, hi, zsqb);
            z2a[q] = za; z2b[q] = zb;
        }

        int bka, bkb; float la, lb;
        vq2(z2a, z2b, zsqa, zsqb, s_cb2n, s_csq2, bka, bkb, la, lb);

        int gya = gy0 + 2*ty;
        obuf[(b*HH + gya    )*WW + gx0 + tx] = (unsigned char)bka;
        obuf[(b*HH + gya + 1)*WW + gx0 + tx] = (unsigned char)bkb;
        loc_loss += la + lb;
        loc_mask |= (1u << bka) | (1u << bkb);
    }
    __syncthreads();
    block_accumulate(loc_loss, loc_mask, slot, red, redu);
}

// ---------------- decode: vectorized LUT gather ----------------
__global__ void k_decode(float* __restrict__ out) {
    int i = blockIdx.x * blockDim.x + threadIdx.x;
    uchar4 k4 = ((const uchar4*)g_idxA)[i];
    ((float4*)out)[i] = make_float4(g_sigD[k4.x], g_sigD[k4.y], g_sigD[k4.z], g_sigD[k4.w]);
}

__global__ void k_final(float* __restrict__ out) {
    float vq = 0.f, us = 0.f;
    #pragma unroll
    for (int s = 0; s < NSTEPS; s++) {
        vq += 1.25f * g_sse[s] / (float)NELEM;
        us += (float)__popc(g_used[s]) / (float)KK;
    }
    out[NPIX]     = vq / (float)NSTEPS;
    out[NPIX + 1] = us / (float)NSTEPS;
}

extern "C" void kernel_launch(void* const* d_in, const int* in_sizes, int n_in,
                              void* d_out, int out_size) {
    const float* x      = (const float*)d_in[0];
    const float* stem_w = (const float*)d_in[1];
    const float* stem_b = (const float*)d_in[2];
    const float* up1_w  = (const float*)d_in[3];
    const float* up1_b  = (const float*)d_in[4];
    const float* up2_w  = (const float*)d_in[5];
    const float* up2_b  = (const float*)d_in[6];
    const float* tau_w  = (const float*)d_in[7];
    const float* tau_b  = (const float*)d_in[8];
    const float* cb     = (const float*)d_in[9];
    const float* dec_w  = (const float*)d_in[10];
    const float* dec_b  = (const float*)d_in[11];
    float* out = (float*)d_out;

    k_tables<<<1, 512>>>(up1_w, tau_w, tau_b, cb, dec_w, dec_b);

    dim3 grid1(WW/16, HH/16, BATCH);
    k_step1<<<grid1, 128>>>(x, stem_w, stem_b, up1_w, up1_b, up2_w, up2_b, tau_w, tau_b, cb);
    for (int s = 1; s < NSTEPS; s++)
        k_step<<<592, 256>>>(up1_b, up2_w, up2_b, cb, s);

    k_decode<<<NPIX/4/256, 256>>>(out);
    k_final<<<1, 1>>>(out);
}

// round 4
// speedup vs baseline: 1.6851x; 1.0853x over previous
#include <cuda_runtime.h>

#define BATCH 32
#define HH 256
#define WW 256
#define CC 16
#define KK 32
#define NSTEPS 5
#define NPIX (BATCH*HH*WW)           // 2097152
#define NELEM (NPIX*CC)
#define NT2 (NPIX/512)               // 4096 tiles of 16x32

typedef unsigned long long ull;

// ---------------- static device scratch ----------------
__device__ float g_M[9*CC*KK];       // [tap][c][k]
__device__ float g_P[CC*KK];         // beta*cb
__device__ float g_Q[CC*KK];         // 1-beta
__device__ float g_csq[KK];
__device__ float g_sigD[KK];
__device__ float g_sse[NSTEPS];
__device__ unsigned g_used[NSTEPS];
__device__ unsigned char g_idxA[NPIX];
__device__ unsigned char g_idxB[NPIX];

// ---------------- f32x2 helpers ----------------
__device__ __forceinline__ ull pack2f(float lo, float hi) {
    ull d;
    asm("mov.b64 %0,{%1,%2};" : "=l"(d) : "r"(__float_as_uint(lo)), "r"(__float_as_uint(hi)));
    return d;
}
__device__ __forceinline__ void unpack2f(ull v, float& lo, float& hi) {
    unsigned a, b;
    asm("mov.b64 {%0,%1},%2;" : "=r"(a), "=r"(b) : "l"(v));
    lo = __uint_as_float(a); hi = __uint_as_float(b);
}
__device__ __forceinline__ ull fma2(ull a, ull b, ull c) {
    ull d;
    asm("fma.rn.f32x2 %0,%1,%2,%3;" : "=l"(d) : "l"(a), "l"(b), "l"(c));
    return d;
}
__device__ __forceinline__ ull add2(ull a, ull b) {
    ull d;
    asm("add.rn.f32x2 %0,%1,%2;" : "=l"(d) : "l"(a), "l"(b));
    return d;
}

// ---------------- table precompute ----------------
__global__ void k_tables(const float* __restrict__ up1_w,
                         const float* __restrict__ tau_w, const float* __restrict__ tau_b,
                         const float* __restrict__ cb,
                         const float* __restrict__ dec_w, const float* __restrict__ dec_b) {
    int tid = threadIdx.x;
    for (int e = tid; e < 9*CC*KK; e += blockDim.x) {
        int k = e & 31; int c = (e >> 5) & 15; int tap = e >> 9;
        float acc = 0.f;
        #pragma unroll
        for (int ci = 0; ci < CC; ci++)
            acc = fmaf(up1_w[(c*CC+ci)*9 + tap], cb[k*CC+ci], acc);
        g_M[e] = acc;
    }
    for (int e = tid; e < CC*KK; e += blockDim.x) {
        int k = e & 31; int c = e >> 5;
        float t = tau_b[c];
        #pragma unroll
        for (int ci = 0; ci < CC; ci++)
            t = fmaf(tau_w[c*CC+ci], cb[k*CC+ci], t);
        float beta = 1.f / (1.f + expf(-t));
        g_P[e] = beta * cb[k*CC+c];
        g_Q[e] = 1.f - beta;
    }
    for (int k = tid; k < KK; k += blockDim.x) {
        float s = 0.f, d = dec_b[0];
        #pragma unroll
        for (int c = 0; c < CC; c++) { float v = cb[k*CC+c]; s = fmaf(v, v, s); d = fmaf(dec_w[c], v, d); }
        g_csq[k] = s;
        g_sigD[k] = 1.f / (1.f + expf(-d));
    }
    if (tid < NSTEPS) { g_sse[tid] = 0.f; g_used[tid] = 0u; }
}

// ---------------- block reduce + atomic ----------------
__device__ __forceinline__ void block_accumulate(float loss, unsigned mask, int slot,
                                                 float* red, unsigned* redu) {
    #pragma unroll
    for (int o = 16; o; o >>= 1) loss += __shfl_xor_sync(0xffffffffu, loss, o);
    mask = __reduce_or_sync(0xffffffffu, mask);
    int lane = threadIdx.x & 31, wid = threadIdx.x >> 5;
    if (lane == 0) { red[wid] = loss; redu[wid] = mask; }
    __syncthreads();
    if (threadIdx.x == 0) {
        float s = 0.f; unsigned m = 0u;
        int nw = blockDim.x >> 5;
        for (int i = 0; i < nw; i++) { s += red[i]; m |= redu[i]; }
        atomicAdd(&g_sse[slot], s);
        atomicOr(&g_used[slot], m);
    }
}

// ---------------- dual-pixel VQ, codebook processed in 2 halves (reg diet) ----------------
__device__ __forceinline__ void vq2_seq(const float* zA, const float* zB,
                                        float zsqa, float zsqb,
                                        const ull* s_cb2n, const ull* s_csq2,
                                        int& bka, int& bkb, float& la, float& lb) {
    float besta = 3.4e38f, bestb = 3.4e38f; bka = 0; bkb = 0;
    #pragma unroll
    for (int h = 0; h < 2; h++) {
        ull da[8], db[8];
        #pragma unroll
        for (int j = 0; j < 8; j++) { ull c0 = s_csq2[h*8 + j]; da[j] = c0; db[j] = c0; }
        #pragma unroll
        for (int c = 0; c < CC; c++) {
            ull za = pack2f(zA[c], zA[c]);
            ull zb = pack2f(zB[c], zB[c]);
            const ulonglong2* cp = (const ulonglong2*)&s_cb2n[c*16 + h*8];
            #pragma unroll
            for (int jj = 0; jj < 4; jj++) {
                ulonglong2 w = cp[jj];
                da[2*jj]   = fma2(za, w.x, da[2*jj]);
                da[2*jj+1] = fma2(za, w.y, da[2*jj+1]);
                db[2*jj]   = fma2(zb, w.x, db[2*jj]);
                db[2*jj+1] = fma2(zb, w.y, db[2*jj+1]);
            }
        }
        #pragma unroll
        for (int j = 0; j < 8; j++) {
            float lo, hi;
            unpack2f(da[j], lo, hi);
            if (lo < besta) { besta = lo; bka = h*16 + 2*j; }
            if (hi < besta) { besta = hi; bka = h*16 + 2*j + 1; }
            unpack2f(db[j], lo, hi);
            if (lo < bestb) { bestb = lo; bkb = h*16 + 2*j; }
            if (hi < bestb) { bestb = hi; bkb = h*16 + 2*j + 1; }
        }
    }
    la = zsqa + besta;
    lb = zsqb + bestb;
}

// ---------------- fused stem + step 1: 16x16 tile, 128 threads, 2 px/thread ----------------
__global__ __launch_bounds__(128, 6)
void k_step1(const float* __restrict__ x,
             const float* __restrict__ stem_w, const float* __restrict__ stem_b,
             const float* __restrict__ up1_w, const float* __restrict__ up1_b,
             const float* __restrict__ up2_w, const float* __restrict__ up2_b,
             const float* __restrict__ tau_w, const float* __restrict__ tau_b,
             const float* __restrict__ cb) {
    __shared__ float xs[20*20];
    __shared__ float s0[CC][18*18];
    __shared__ ull s_w2[CC*9*8];
    __shared__ ull s_tw2[CC*8], s_u2w2[CC*8];
    __shared__ ull s_cb2n[CC*16];
    __shared__ ull s_csq2[16];
    __shared__ ull s_bu1[8], s_bu2[8], s_bt[8];
    __shared__ float red[4]; __shared__ unsigned redu[4];

    int tid = threadIdx.x;
    int tx = tid & 15, ty = tid >> 4;      // ty 0..7, rows 2ty, 2ty+1
    int gx0 = blockIdx.x * 16, gy0 = blockIdx.y * 16, b = blockIdx.z;
    const float* xb = x + b * HH * WW;

    for (int e = tid; e < CC*9*8; e += 128) {
        int q = e & 7; int t = (e >> 3) % 9; int ci = e / 72;
        s_w2[e] = pack2f(up1_w[(2*q*CC + ci)*9 + t], up1_w[((2*q+1)*CC + ci)*9 + t]);
    }
    for (int e = tid; e < CC*8; e += 128) {
        int q = e & 7; int ci = e >> 3;
        s_tw2[e]  = pack2f(tau_w[2*q*CC + ci],  tau_w[(2*q+1)*CC + ci]);
        s_u2w2[e] = pack2f(up2_w[2*q*CC + ci],  up2_w[(2*q+1)*CC + ci]);
    }
    for (int e = tid; e < CC*16; e += 128) {
        int j = e & 15; int c = e >> 4;
        s_cb2n[e] = pack2f(-2.f*cb[2*j*CC + c], -2.f*cb[(2*j+1)*CC + c]);
    }
    if (tid < 16) s_csq2[tid] = pack2f(g_csq[2*tid], g_csq[2*tid+1]);
    if (tid < 8) {
        s_bu1[tid] = pack2f(up1_b[2*tid], up1_b[2*tid+1]);
        s_bu2[tid] = pack2f(up2_b[2*tid], up2_b[2*tid+1]);
        s_bt[tid]  = pack2f(tau_b[2*tid], tau_b[2*tid+1]);
    }
    for (int p = tid; p < 400; p += 128) {
        int iy = p / 20, ix = p % 20;
        int gy = gy0 - 2 + iy, gx = gx0 - 2 + ix;
        xs[p] = (gy >= 0 && gy < HH && gx >= 0 && gx < WW) ? xb[gy*WW + gx] : 0.f;
    }
    __syncthreads();

    // stem over 18x18 halo
    for (int p = tid; p < 324; p += 128) {
        int ly = p / 18, lx = p % 18;
        int gy = gy0 - 1 + ly, gx = gx0 - 1 + lx;
        bool inb = (gy >= 0 && gy < HH && gx >= 0 && gx < WW);
        #pragma unroll
        for (int c = 0; c < CC; c++) {
            float acc = 0.f;
            if (inb) {
                acc = stem_b[c];
                #pragma unroll
                for (int t = 0; t < 9; t++)
                    acc = fmaf(stem_w[c*9 + t], xs[(ly + t/3)*20 + (lx + t%3)], acc);
                acc = fmaxf(acc, 0.f);
            }
            s0[c][p] = acc;
        }
    }
    __syncthreads();

    // ---- conv3x3 16->16, 2 px/thread ----
    ull y2a[8], y2b[8];
    #pragma unroll
    for (int q = 0; q < 8; q++) { y2a[q] = s_bu1[q]; y2b[q] = s_bu1[q]; }
    #pragma unroll 4
    for (int ci = 0; ci < CC; ci++) {
        const float* s0p = &s0[ci][0];
        #pragma unroll
        for (int tc = 0; tc < 3; tc++) {
            float v0 = s0p[(2*ty+0)*18 + tx + tc];
            float v1 = s0p[(2*ty+1)*18 + tx + tc];
            float v2 = s0p[(2*ty+2)*18 + tx + tc];
            float v3 = s0p[(2*ty+3)*18 + tx + tc];
            #pragma unroll
            for (int tr = 0; tr < 3; tr++) {
                int t = tr*3 + tc;
                float va = (tr == 0) ? v0 : ((tr == 1) ? v1 : v2);
                float vb = (tr == 0) ? v1 : ((tr == 1) ? v2 : v3);
                ull vva = pack2f(va, va), vvb = pack2f(vb, vb);
                const ulonglong2* wp = (const ulonglong2*)&s_w2[(ci*9 + t)*8];
                #pragma unroll
                for (int qq = 0; qq < 4; qq++) {
                    ulonglong2 w = wp[qq];
                    y2a[2*qq]   = fma2(vva, w.x, y2a[2*qq]);
                    y2a[2*qq+1] = fma2(vva, w.y, y2a[2*qq+1]);
                    y2b[2*qq]   = fma2(vvb, w.x, y2b[2*qq]);
                    y2b[2*qq+1] = fma2(vvb, w.y, y2b[2*qq+1]);
                }
            }
        }
    }

    // ---- delta = up2 @ relu(y), unpack y on the fly ----
    ull d2a[8], d2b[8];
    #pragma unroll
    for (int q = 0; q < 8; q++) { d2a[q] = s_bu2[q]; d2b[q] = s_bu2[q]; }
    #pragma unroll
    for (int q = 0; q < 8; q++) {
        float a0, a1, b0, b1;
        unpack2f(y2a[q], a0, a1); unpack2f(y2b[q], b0, b1);
        a0 = fmaxf(a0, 0.f); a1 = fmaxf(a1, 0.f);
        b0 = fmaxf(b0, 0.f); b1 = fmaxf(b1, 0.f);
        #pragma unroll
        for (int s = 0; s < 2; s++) {
            int ci = 2*q + s;
            float fa = s ? a1 : a0, fb = s ? b1 : b0;
            ull va = pack2f(fa, fa), vb = pack2f(fb, fb);
            const ulonglong2* wp = (const ulonglong2*)&s_u2w2[ci*8];
            #pragma unroll
            for (int qq = 0; qq < 4; qq++) {
                ulonglong2 w = wp[qq];
                d2a[2*qq]   = fma2(va, w.x, d2a[2*qq]);
                d2a[2*qq+1] = fma2(va, w.y, d2a[2*qq+1]);
                d2b[2*qq]   = fma2(vb, w.x, d2b[2*qq]);
                d2b[2*qq+1] = fma2(vb, w.y, d2b[2*qq+1]);
            }
        }
    }

    // ---- tau (center values read from smem, not registers) ----
    int ctra = (2*ty+1)*18 + (tx+1);
    int ctrb = (2*ty+2)*18 + (tx+1);
    ull t2a[8], t2b[8];
    #pragma unroll
    for (int q = 0; q < 8; q++) { t2a[q] = s_bt[q]; t2b[q] = s_bt[q]; }
    #pragma unroll 4
    for (int ci = 0; ci < CC; ci++) {
        float fa = s0[ci][ctra], fb = s0[ci][ctrb];
        ull va = pack2f(fa, fa), vb = pack2f(fb, fb);
        const ulonglong2* wp = (const ulonglong2*)&s_tw2[ci*8];
        #pragma unroll
        for (int qq = 0; qq < 4; qq++) {
            ulonglong2 w = wp[qq];
            t2a[2*qq]   = fma2(va, w.x, t2a[2*qq]);
            t2a[2*qq+1] = fma2(va, w.y, t2a[2*qq+1]);
            t2b[2*qq]   = fma2(vb, w.x, t2b[2*qq]);
            t2b[2*qq+1] = fma2(vb, w.y, t2b[2*qq+1]);
        }
    }

    // ---- blend + zsq (center values re-read from smem) ----
    float zA[CC], zB[CC]; float zsqa = 0.f, zsqb = 0.f;
    #pragma unroll
    for (int q = 0; q < 8; q++) {
        float tlo, thi, dlo, dhi;
        unpack2f(t2a[q], tlo, thi); unpack2f(d2a[q], dlo, dhi);
        {
            float blo = 1.f / (1.f + __expf(-tlo));
            float bhi = 1.f / (1.f + __expf(-thi));
            float zlo = fmaf(blo, s0[2*q][ctra],   (1.f - blo) * dlo);
            float zhi = fmaf(bhi, s0[2*q+1][ctra], (1.f - bhi) * dhi);
            zsqa = fmaf(zlo, zlo, zsqa); zsqa = fmaf(zhi, zhi, zsqa);
            zA[2*q] = zlo; zA[2*q+1] = zhi;
        }
        unpack2f(t2b[q], tlo, thi); unpack2f(d2b[q], dlo, dhi);
        {
            float blo = 1.f / (1.f + __expf(-tlo));
            float bhi = 1.f / (1.f + __expf(-thi));
            float zlo = fmaf(blo, s0[2*q][ctrb],   (1.f - blo) * dlo);
            float zhi = fmaf(bhi, s0[2*q+1][ctrb], (1.f - bhi) * dhi);
            zsqb = fmaf(zlo, zlo, zsqb); zsqb = fmaf(zhi, zhi, zsqb);
            zB[2*q] = zlo; zB[2*q+1] = zhi;
        }
    }

    int bka, bkb; float la, lb;
    vq2_seq(zA, zB, zsqa, zsqb, s_cb2n, s_csq2, bka, bkb, la, lb);

    int gya = gy0 + 2*ty;
    g_idxA[(b*HH + gya    )*WW + gx0 + tx] = (unsigned char)bka;
    g_idxA[(b*HH + gya + 1)*WW + gx0 + tx] = (unsigned char)bkb;
    block_accumulate(la + lb, (1u << bka) | (1u << bkb), 0, red, redu);
}

// ---------------- steps 2..5: persistent, 16x32 tile, 256 threads, 2 px/thread ----------------
__global__ __launch_bounds__(256, 3)
void k_step(const float* __restrict__ up1_b, const float* __restrict__ up2_w,
            const float* __restrict__ up2_b, const float* __restrict__ cb, int slot) {
    __shared__ ull s_M2[9*8*33];        // [t][q][k], sentinel k=32 -> 0
    __shared__ ull s_P2[8*32], s_Q2[8*32];
    __shared__ ull s_cb2n[CC*16];
    __shared__ ull s_csq2[16];
    __shared__ ull s_bu1[8], s_bu2[8];
    __shared__ ull s_u2w2[CC*8];
    __shared__ unsigned char s_idx[34*18];
    __shared__ float red[8]; __shared__ unsigned redu[8];

    int tid = threadIdx.x;
    for (int e = tid; e < 9*8*33; e += 256) {
        int k = e % 33; int q = (e/33) & 7; int t = e/(33*8);
        float lo = 0.f, hi = 0.f;
        if (k < 32) { lo = g_M[(t*CC + 2*q)*KK + k]; hi = g_M[(t*CC + 2*q+1)*KK + k]; }
        s_M2[e] = pack2f(lo, hi);
    }
    for (int e = tid; e < 8*32; e += 256) {
        int k = e & 31; int q = e >> 5;
        s_P2[e] = pack2f(g_P[2*q*KK + k], g_P[(2*q+1)*KK + k]);
        s_Q2[e] = pack2f(g_Q[2*q*KK + k], g_Q[(2*q+1)*KK + k]);
    }
    for (int e = tid; e < CC*16; e += 256) {
        int j = e & 15; int c = e >> 4;
        s_cb2n[e] = pack2f(-2.f*cb[2*j*CC + c], -2.f*cb[(2*j+1)*CC + c]);
    }
    if (tid < 16) s_csq2[tid] = pack2f(g_csq[2*tid], g_csq[2*tid+1]);
    if (tid < 8) {
        s_bu1[tid] = pack2f(up1_b[2*tid], up1_b[2*tid+1]);
        s_bu2[tid] = pack2f(up2_b[2*tid], up2_b[2*tid+1]);
    }
    for (int e = tid; e < CC*8; e += 256) {
        int q = e & 7; int ci = e >> 3;
        s_u2w2[e] = pack2f(up2_w[2*q*CC + ci], up2_w[(2*q+1)*CC + ci]);
    }

    const unsigned char* ibuf = (slot & 1) ? g_idxA : g_idxB;
    unsigned char* obuf       = (slot & 1) ? g_idxB : g_idxA;

    int tx = tid & 15, ty = tid >> 4;   // ty 0..15, rows 2ty, 2ty+1 of 32-row tile
    float loc_loss = 0.f; unsigned loc_mask = 0u;

    for (int tile = blockIdx.x; tile < NT2; tile += gridDim.x) {
        int b = tile >> 7; int rem = tile & 127;
        int gy0 = (rem >> 4) << 5, gx0 = (rem & 15) << 4;
        const unsigned char* ib = ibuf + b * HH * WW;

        __syncthreads();
        for (int p = tid; p < 34*18; p += 256) {
            int iy = p / 18, ix = p % 18;
            int gy = gy0 - 1 + iy, gx = gx0 - 1 + ix;
            s_idx[p] = (gy >= 0 && gy < HH && gx >= 0 && gx < WW) ? ib[gy*WW + gx] : 32;
        }
        __syncthreads();

        // conv via table adds; idx rows shared between the 2 pixels
        ull y2a[8], y2b[8];
        #pragma unroll
        for (int q = 0; q < 8; q++) { y2a[q] = s_bu1[q]; y2b[q] = s_bu1[q]; }
        #pragma unroll
        for (int tc = 0; tc < 3; tc++) {
            int i0 = s_idx[(2*ty+0)*18 + tx + tc];
            int i1 = s_idx[(2*ty+1)*18 + tx + tc];
            int i2 = s_idx[(2*ty+2)*18 + tx + tc];
            int i3 = s_idx[(2*ty+3)*18 + tx + tc];
            #pragma unroll
            for (int tr = 0; tr < 3; tr++) {
                int t = tr*3 + tc;
                int ka = (tr == 0) ? i0 : ((tr == 1) ? i1 : i2);
                int kb = (tr == 0) ? i1 : ((tr == 1) ? i2 : i3);
                const ull* Ma = &s_M2[t*8*33 + ka];
                const ull* Mb = &s_M2[t*8*33 + kb];
                #pragma unroll
                for (int q = 0; q < 8; q++) {
                    y2a[q] = add2(y2a[q], Ma[q*33]);
                    y2b[q] = add2(y2b[q], Mb[q*33]);
                }
            }
        }

        // delta, relu+unpack on the fly
        ull d2a[8], d2b[8];
        #pragma unroll
        for (int q = 0; q < 8; q++) { d2a[q] = s_bu2[q]; d2b[q] = s_bu2[q]; }
        #pragma unroll
        for (int q = 0; q < 8; q++) {
            float a0, a1, b0, b1;
            unpack2f(y2a[q], a0, a1); unpack2f(y2b[q], b0, b1);
            a0 = fmaxf(a0, 0.f); a1 = fmaxf(a1, 0.f);
            b0 = fmaxf(b0, 0.f); b1 = fmaxf(b1, 0.f);
            #pragma unroll
            for (int s = 0; s < 2; s++) {
                int ci = 2*q + s;
                float fa = s ? a1 : a0, fb = s ? b1 : b0;
                ull va = pack2f(fa, fa), vb = pack2f(fb, fb);
                const ulonglong2* wp = (const ulonglong2*)&s_u2w2[ci*8];
                #pragma unroll
                for (int qq = 0; qq < 4; qq++) {
                    ulonglong2 w = wp[qq];
                    d2a[2*qq]   = fma2(va, w.x, d2a[2*qq]);
                    d2a[2*qq+1] = fma2(va, w.y, d2a[2*qq+1]);
                    d2b[2*qq]   = fma2(vb, w.x, d2b[2*qq]);
                    d2b[2*qq+1] = fma2(vb, w.y, d2b[2*qq+1]);
                }
            }
        }

        // blend via P/Q tables on center codes
        int kca = s_idx[(2*ty+1)*18 + tx + 1];
        int kcb = s_idx[(2*ty+2)*18 + tx + 1];
        float zA[CC], zB[CC]; float zsqa = 0.f, zsqb = 0.f;
        #pragma unroll
        for (int q = 0; q < 8; q++) {
            ull za = fma2(s_Q2[q*32 + kca], d2a[q], s_P2[q*32 + kca]);
            ull zb = fma2(s_Q2[q*32 + kcb], d2b[q], s_P2[q*32 + kcb]);
            float lo, hi;
            unpack2f(za, lo, hi); zsqa = fmaf(lo, lo, zsqa); zsqa = fmaf(hi, hi, zsqa);
            zA[2*q] = lo; zA[2*q+1] = hi;
            unpack2f(zb, lo, hi); zsqb = fmaf(lo, lo, zsqb); zsqb = fmaf(hi, hi, zsqb);
            zB[2*q] = lo; zB[2*q+1] = hi;
        }

        int bka, bkb; float la, lb;
        vq2_seq(zA, zB, zsqa, zsqb, s_cb2n, s_csq2, bka, bkb, la, lb);

        int gya = gy0 + 2*ty;
        obuf[(b*HH + gya    )*WW + gx0 + tx] = (unsigned char)bka;
        obuf[(b*HH + gya + 1)*WW + gx0 + tx] = (unsigned char)bkb;
        loc_loss += la + lb;
        loc_mask |= (1u << bka) | (1u << bkb);
    }
    __syncthreads();
    block_accumulate(loc_loss, loc_mask, slot, red, redu);
}

// ---------------- decode: vectorized LUT gather ----------------
__global__ void k_decode(float* __restrict__ out) {
    int i = blockIdx.x * blockDim.x + threadIdx.x;
    uchar4 k4 = ((const uchar4*)g_idxA)[i];
    ((float4*)out)[i] = make_float4(g_sigD[k4.x], g_sigD[k4.y], g_sigD[k4.z], g_sigD[k4.w]);
}

__global__ void k_final(float* __restrict__ out) {
    float vq = 0.f, us = 0.f;
    #pragma unroll
    for (int s = 0; s < NSTEPS; s++) {
        vq += 1.25f * g_sse[s] / (float)NELEM;
        us += (float)__popc(g_used[s]) / (float)KK;
    }
    out[NPIX]     = vq / (float)NSTEPS;
    out[NPIX + 1] = us / (float)NSTEPS;
}

extern "C" void kernel_launch(void* const* d_in, const int* in_sizes, int n_in,
                              void* d_out, int out_size) {
    const float* x      = (const float*)d_in[0];
    const float* stem_w = (const float*)d_in[1];
    const float* stem_b = (const float*)d_in[2];
    const float* up1_w  = (const float*)d_in[3];
    const float* up1_b  = (const float*)d_in[4];
    const float* up2_w  = (const float*)d_in[5];
    const float* up2_b  = (const float*)d_in[6];
    const float* tau_w  = (const float*)d_in[7];
    const float* tau_b  = (const float*)d_in[8];
    const float* cb     = (const float*)d_in[9];
    const float* dec_w  = (const float*)d_in[10];
    const float* dec_b  = (const float*)d_in[11];
    float* out = (float*)d_out;

    k_tables<<<1, 512>>>(up1_w, tau_w, tau_b, cb, dec_w, dec_b);

    dim3 grid1(WW/16, HH/16, BATCH);
    k_step1<<<grid1, 128>>>(x, stem_w, stem_b, up1_w, up1_b, up2_w, up2_b, tau_w, tau_b, cb);
    for (int s = 1; s < NSTEPS; s++)
        k_step<<<1332, 256>>>(up1_b, up2_w, up2_b, cb, s);

    k_decode<<<NPIX/4/256, 256>>>(out);
    k_final<<<1, 1>>>(out);
}